// round 14
// baseline (speedup 1.0000x reference)
#include <cuda_runtime.h>

#define FULL 0xffffffffu
#define WPB 4            // warps (rays) per block
#define HN 64
#define NPAIR 32
#define LVL 4
#define SN 64

__device__ __forceinline__ float fast_ex2(float x) {
    float y; asm("ex2.approx.f32 %0, %1;" : "=f"(y) : "f"(x)); return y;
}
__device__ __forceinline__ float fast_rcp(float x) {
    float y; asm("rcp.approx.f32 %0, %1;" : "=f"(y) : "f"(x)); return y;
}
__device__ __forceinline__ float fast_sqrt(float x) {
    float y; asm("sqrt.approx.f32 %0, %1;" : "=f"(y) : "f"(x)); return y;
}
__device__ __forceinline__ unsigned long long pk2(float lo, float hi) {
    unsigned long long r; asm("mov.b64 %0, {%1, %2};" : "=l"(r) : "f"(lo), "f"(hi)); return r;
}
__device__ __forceinline__ void upk2(unsigned long long v, float& lo, float& hi) {
    asm("mov.b64 {%0, %1}, %2;" : "=f"(lo), "=f"(hi) : "l"(v));
}
__device__ __forceinline__ unsigned long long fma2(unsigned long long a,
                                                   unsigned long long b,
                                                   unsigned long long c) {
    unsigned long long d;
    asm("fma.rn.f32x2 %0, %1, %2, %3;" : "=l"(d) : "l"(a), "l"(b), "l"(c));
    return d;
}
__device__ __forceinline__ unsigned long long mul2(unsigned long long a,
                                                   unsigned long long b) {
    unsigned long long d;
    asm("mul.rn.f32x2 %0, %1, %2;" : "=l"(d) : "l"(a), "l"(b));
    return d;
}

__global__ __launch_bounds__(128, 12)
void mr_kernel(const float* __restrict__ rays_o,
               const float* __restrict__ rays_d,
               const float* __restrict__ levels,
               const float* __restrict__ W1,
               const float* __restrict__ b1,
               const float* __restrict__ W2,
               const float* __restrict__ b2,
               float* __restrict__ out,
               int N, int do_mask)
{
    // pair-interleaved raw weights, scaled by K = 2*log2(e):
    //   sPA[p] = (Kwx_j, Kwx_j1, Kwy_j, Kwy_j1)
    //   sPB[p] = (Kwz_j, Kwz_j1, Kb1_j, Kb1_j1)
    //   sM2[p] = (-2w2_j, -2w2_j1)
    __shared__ float4 sPA[NPAIR];
    __shared__ float4 sPB[NPAIR];
    __shared__ float2 sM2[NPAIR];
    __shared__ float  slev[LVL];
    __shared__ float  sw2sum;
    __shared__ float  sscal[WPB][SN];
    __shared__ float4 sGH[WPB][NPAIR];   // per-ray affine coeffs (g0,g1,h0,h1)

    const float K = 2.8853900817779268f;   // 2*log2(e)

    int tid = threadIdx.x;
    if (tid < NPAIR) {
        int j = 2*tid, j1 = j + 1;
        sPA[tid] = make_float4(K*W1[j], K*W1[j1], K*W1[HN + j], K*W1[HN + j1]);
        sPB[tid] = make_float4(K*W1[2*HN + j], K*W1[2*HN + j1], K*b1[j], K*b1[j1]);
        sM2[tid] = make_float2(-2.0f*W2[j], -2.0f*W2[j1]);
    }
    if (tid < LVL) slev[tid] = levels[tid];
    if (tid == 0) {
        float s = 0.0f;
        #pragma unroll 8
        for (int j = 0; j < HN; ++j) s += W2[j];
        sw2sum = s;
    }
    __syncthreads();

    float addc  = b2[0] + 1.0f;          // b2 + R0
    float cbase = addc + sw2sum;         // constant after the -2*w2*r fold

    int lane = tid & 31;
    int warp = tid >> 5;
    int ray  = blockIdx.x * WPB + warp;
    if (ray >= N) return;

    float ox = rays_o[ray*3+0], oy = rays_o[ray*3+1], oz = rays_o[ray*3+2];
    float dx = rays_d[ray*3+0], dy = rays_d[ray*3+1], dz = rays_d[ray*3+2];

    // sphere bounds
    float bq = ox*dx + oy*dy + oz*dz;
    float cq = ox*ox + oy*oy + oz*oz - 9.0f;
    float disc = bq*bq - cq;
    bool  hit = disc > 0.0f;
    float sq = sqrtf(hit ? disc : 1.0f);
    float dnear = fmaxf(-bq - sq, 0.0f);
    float dfar  = fminf(-bq + sq, 100.0f);
    bool  mask_bound = hit && (dnear < dfar);

    float* scal = sscal[warp];

    // ---------------- per-ray affine coefficients: pre_j(t) = g_j * t + h_j ----------------
    {
        ulonglong2 A  = *reinterpret_cast<const ulonglong2*>(&sPA[lane]); // (wx pair, wy pair)
        ulonglong2 Bv = *reinterpret_cast<const ulonglong2*>(&sPB[lane]); // (wz pair, b pair)
        unsigned long long DX2 = pk2(dx,dx), DY2 = pk2(dy,dy), DZ2 = pk2(dz,dz);
        unsigned long long OX2 = pk2(ox,ox), OY2 = pk2(oy,oy), OZ2 = pk2(oz,oz);
        unsigned long long G2 = fma2(A.x, DX2, fma2(A.y, DY2, mul2(Bv.x, DZ2)));
        unsigned long long H2 = fma2(A.x, OX2, fma2(A.y, OY2, fma2(Bv.x, OZ2, Bv.y)));
        ulonglong2 gh; gh.x = G2; gh.y = H2;
        *reinterpret_cast<ulonglong2*>(&sGH[warp][lane]) = gh;
    }
    __syncwarp();

    // ---------------- Phase A: sample evals (2 per lane, sample-major halves) ----------------
    unsigned vm0 = 0u, vm1 = 0u;
    float minv = 3.402823466e38f;
    int   minj = 0;
    #pragma unroll
    for (int half = 0; half < 2; ++half) {
        int s = lane + half*32;
        float t = (float)s / 63.0f;
        float dd = dnear*(1.0f - t) + dfar*t;
        unsigned long long DD2 = pk2(dd, dd);
        // exact elementwise norm (matches reference boundary behavior)
        float x0 = fmaf(dx, dd, ox);
        float x1 = fmaf(dy, dd, oy);
        float x2 = fmaf(dz, dd, oz);
        float nrm = fast_sqrt(fmaf(x0, x0, fmaf(x1, x1, x2*x2)));
        float acc0 = 0.0f, acc1 = 0.0f;
        #pragma unroll 4
        for (int g = 0; g < 16; ++g) {
            ulonglong2 GH0 = *reinterpret_cast<const ulonglong2*>(&sGH[warp][2*g]);
            ulonglong2 GH1 = *reinterpret_cast<const ulonglong2*>(&sGH[warp][2*g+1]);
            float4 m2q = *reinterpret_cast<const float4*>(&sM2[2*g]);
            float u01 = m2q.x + m2q.y;
            float u23 = m2q.z + m2q.w;
            unsigned long long pA = fma2(DD2, GH0.x, GH0.y);
            unsigned long long pB = fma2(DD2, GH1.x, GH1.y);
            float p0, p1, p2, p3;
            upk2(pA, p0, p1); upk2(pB, p2, p3);
            float e0 = fast_ex2(p0), e1 = fast_ex2(p1);
            float e2 = fast_ex2(p2), e3 = fast_ex2(p3);
            float A0 = 1.0f + e0, A2 = 1.0f + e2;
            float b01 = fmaf(A0, e1, A0);     // (1+e0)(1+e1)
            float b23 = fmaf(A2, e3, A2);     // (1+e2)(1+e3)
            float rp  = fast_rcp(b01 * b23);
            float q01 = b23 * rp;             // 1/b01
            float q23 = b01 * rp;             // 1/b23
            float N01 = fmaf(m2q.x, e1, fmaf(m2q.y, e0, u01));
            float N23 = fmaf(m2q.z, e3, fmaf(m2q.w, e2, u23));
            acc0 = fmaf(N01, q01, acc0);
            acc1 = fmaf(N23, q23, acc1);
        }
        float sv = (acc0 + acc1) + cbase - nrm;
        bool valid = nrm < 3.0f;
        scal[s] = sv;
        unsigned bal = __ballot_sync(FULL, valid);
        if (half == 0) vm0 = bal; else vm1 = bal;
        if (s >= 1 && sv < minv) { minv = sv; minj = s - 1; }
    }
    __syncwarp();

    // warp-reduce argmin (first occurrence on ties -> smaller index)
    #pragma unroll
    for (int off = 16; off >= 1; off >>= 1) {
        float ov = __shfl_xor_sync(FULL, minv, off);
        int   oj = __shfl_xor_sync(FULL, minj, off);
        if (ov < minv || (ov == minv && oj < minj)) { minv = ov; minj = oj; }
    }

    // ---------------- Phase B: interval search, 8 lanes per level ----------------
    int   mylev = lane & 3;
    int   grp   = lane >> 2;
    float lval  = slev[mylev];
    float brank = -3.402823466e38f;
    int   bj    = 63;
    int   anyi  = 0;
    #pragma unroll
    for (int k = 0; k < 8; ++k) {
        int j = grp*8 + k;
        if (j < 63) {
            float sf = scal[j], sb = scal[j+1];
            float diff = lval - sb;
            float sgn = (diff > 0.0f) ? 1.0f : ((diff < 0.0f) ? -1.0f : 0.0f);
            float rank = sgn * (float)(63 - j);
            if (rank > brank) { brank = rank; bj = j; }   // ascending j -> first max kept
            unsigned wv  = (j  < 32) ? vm0 : vm1;
            unsigned wv1 = (j+1 < 32) ? vm0 : vm1;
            bool vj  = (wv  >> (j & 31)) & 1u;
            bool vj1 = (wv1 >> ((j+1) & 31)) & 1u;
            if ((sf >= lval) && (lval >= sb) && vj && vj1) anyi = 1;
        }
    }
    #pragma unroll
    for (int off = 4; off <= 16; off <<= 1) {
        float orank = __shfl_xor_sync(FULL, brank, off);
        int   obj   = __shfl_xor_sync(FULL, bj, off);
        int   oany  = __shfl_xor_sync(FULL, anyi, off);
        anyi |= oany;
        if (orank > brank || (orank == brank && obj < bj)) { brank = orank; bj = obj; }
    }
    int idxsel = anyi ? bj : minj;   // valid at lanes 0..3 (lane L holds level L)

    // ---------------- Phase C: all 4 levels concurrently, 8 lanes per level ----------------
    int levgrp = lane >> 3;          // my level (0..3)
    int sub    = lane & 7;           // my slot within the level group
    float lv   = slev[levgrp];
    int  idxL  = __shfl_sync(FULL, idxsel, levgrp);

    // my 4 unit-pairs: p = sub*4 .. sub*4+3; m2 hoisted into regs
    float4 m2a = *reinterpret_cast<const float4*>(&sM2[sub*4]);     // pairs 4s, 4s+1
    float4 m2b = *reinterpret_cast<const float4*>(&sM2[sub*4+2]);   // pairs 4s+2, 4s+3
    float ua01 = m2a.x + m2a.y, ua23 = m2a.z + m2a.w;
    float ub01 = m2b.x + m2b.y, ub23 = m2b.z + m2b.w;
    float wq = -0.5f * (ua01 + ua23 + ub01 + ub23);

    float tF = (float)idxL / 63.0f;
    float tB = (float)(idxL+1) / 63.0f;
    float d_front = dnear*(1.0f - tF) + dfar*tF;
    float d_back  = dnear*(1.0f - tB) + dfar*tB;
    float s_front = scal[idxL], s_back = scal[idxL+1];
    bool  m_int = (s_front >= lv) && (lv >= s_back);
    float sdiff = s_front - s_back;
    bool  mvd = fabsf(sdiff) > 1e-4f;
    bool  m_sec = m_int && mvd;
    float d_sec = ((lv - s_back)*d_front + (s_front - lv)*d_back) / (mvd ? sdiff : 1.0f);
    float d_init = m_sec ? d_sec : d_back;

    float dfs = d_front, dbs = d_back, sfs = s_front, sbs = s_back, dcur = d_init;
    #pragma unroll
    for (int it = 0; it < 4; ++it) {
        unsigned long long DC2 = pk2(dcur, dcur);
        float partial = wq;
        #pragma unroll
        for (int gg = 0; gg < 2; ++gg) {
            int p = sub*4 + gg*2;
            ulonglong2 GHa = *reinterpret_cast<const ulonglong2*>(&sGH[warp][p]);
            ulonglong2 GHb = *reinterpret_cast<const ulonglong2*>(&sGH[warp][p+1]);
            float4 m2q = gg ? m2b : m2a;
            float u01 = gg ? ub01 : ua01;
            float u23 = gg ? ub23 : ua23;
            unsigned long long pA = fma2(DC2, GHa.x, GHa.y);
            unsigned long long pB = fma2(DC2, GHb.x, GHb.y);
            float p0, p1, p2, p3;
            upk2(pA, p0, p1); upk2(pB, p2, p3);
            float e0 = fast_ex2(p0), e1 = fast_ex2(p1);
            float e2 = fast_ex2(p2), e3 = fast_ex2(p3);
            float A0 = 1.0f + e0, A2 = 1.0f + e2;
            float b01 = fmaf(A0, e1, A0);
            float b23 = fmaf(A2, e3, A2);
            float rp  = fast_rcp(b01 * b23);
            float q01 = b23 * rp;
            float q23 = b01 * rp;
            float N01 = fmaf(m2q.x, e1, fmaf(m2q.y, e0, u01));
            float N23 = fmaf(m2q.z, e3, fmaf(m2q.w, e2, u23));
            partial = fmaf(N01, q01, partial);
            partial = fmaf(N23, q23, partial);
        }
        // reduce over the 8 lanes of my level group (aligned; xor 1,2,4 stays in group)
        #pragma unroll
        for (int off = 1; off <= 4; off <<= 1)
            partial += __shfl_xor_sync(FULL, partial, off);   // identical across group
        // exact elementwise norm
        float x0 = fmaf(dx, dcur, ox);
        float x1 = fmaf(dy, dcur, oy);
        float x2 = fmaf(dz, dcur, oz);
        float nrm = fast_sqrt(fmaf(x0, x0, fmaf(x1, x1, x2*x2)));
        float s_mid = partial + addc - nrm;
        bool mv = nrm < 3.0f;
        bool upf = (s_mid > lv) && mv;
        bool upb = (s_mid < lv) && mv;
        if (upf) { dfs = dcur; sfs = s_mid; }
        if (upb) { dbs = dcur; sbs = s_mid; }
        float sd = sfs - sbs;
        bool ok = fabsf(sd) > 1e-4f;
        float dn = ((lv - sbs)*dfs + (sfs - lv)*dbs) / (ok ? sd : 1.0f);
        dcur = ok ? dn : dcur;
    }
    float dL = m_sec ? dcur : d_init;
    int   mL = m_int ? 1 : 0;

    // gather the 4 per-level results (levels live at lanes 0,8,16,24)
    float d0 = __shfl_sync(FULL, dL, 0);
    float d1 = __shfl_sync(FULL, dL, 8);
    float d2 = __shfl_sync(FULL, dL, 16);
    float d3 = __shfl_sync(FULL, dL, 24);
    int   m0 = __shfl_sync(FULL, mL, 0);
    int   m1 = __shfl_sync(FULL, mL, 8);
    int   m2v = __shfl_sync(FULL, mL, 16);
    int   m3 = __shfl_sync(FULL, mL, 24);

    // ---------------- stable ascending sort of 4 (adjacent swaps, strict <) ----------------
    #define CSW(da,ma,db,mb) do { if ((db) < (da)) { float _t=(da); (da)=(db); (db)=_t; int _m=(ma); (ma)=(mb); (mb)=_m; } } while(0)
    CSW(d0,m0,d1,m1); CSW(d1,m1,d2,m2v); CSW(d2,m2v,d3,m3);
    CSW(d0,m0,d1,m1); CSW(d1,m1,d2,m2v);
    CSW(d0,m0,d1,m1);
    #undef CSW

    if (lane == 0) {
        float4 dv = mask_bound ? make_float4(d0, d1, d2, d3)
                               : make_float4(0.f, 0.f, 0.f, 0.f);
        *reinterpret_cast<float4*>(out + (size_t)ray*4) = dv;
        if (do_mask) {
            float4 mv4 = mask_bound ? make_float4((float)m0, (float)m1, (float)m2v, (float)m3)
                                    : make_float4(0.f, 0.f, 0.f, 0.f);
            *reinterpret_cast<float4*>(out + (size_t)N*4 + (size_t)ray*4) = mv4;
        }
    }
}

extern "C" void kernel_launch(void* const* d_in, const int* in_sizes, int n_in,
                              void* d_out, int out_size) {
    const float* rays_o = (const float*)d_in[0];
    const float* rays_d = (const float*)d_in[1];
    const float* levels = (const float*)d_in[2];
    const float* W1     = (const float*)d_in[3];
    const float* b1     = (const float*)d_in[4];
    const float* W2     = (const float*)d_in[5];
    const float* b2     = (const float*)d_in[6];
    int N = in_sizes[0] / 3;
    int do_mask = (out_size >= 2 * N * LVL) ? 1 : 0;
    int blocks = (N + WPB - 1) / WPB;
    mr_kernel<<<blocks, 128>>>(rays_o, rays_d, levels, W1, b1, W2, b2,
                               (float*)d_out, N, do_mask);
}

// round 15
// speedup vs baseline: 1.0716x; 1.0716x over previous
#include <cuda_runtime.h>

#define FULL 0xffffffffu
#define WPB 4            // warps (rays) per block
#define HN 64
#define NPAIR 32
#define LVL 4
#define SN 64

__device__ __forceinline__ float fast_ex2(float x) {
    float y; asm("ex2.approx.f32 %0, %1;" : "=f"(y) : "f"(x)); return y;
}
__device__ __forceinline__ float fast_rcp(float x) {
    float y; asm("rcp.approx.f32 %0, %1;" : "=f"(y) : "f"(x)); return y;
}
__device__ __forceinline__ float fast_sqrt(float x) {
    float y; asm("sqrt.approx.f32 %0, %1;" : "=f"(y) : "f"(x)); return y;
}
__device__ __forceinline__ unsigned long long pk2(float lo, float hi) {
    unsigned long long r; asm("mov.b64 %0, {%1, %2};" : "=l"(r) : "f"(lo), "f"(hi)); return r;
}
__device__ __forceinline__ void upk2(unsigned long long v, float& lo, float& hi) {
    asm("mov.b64 {%0, %1}, %2;" : "=f"(lo), "=f"(hi) : "l"(v));
}
__device__ __forceinline__ unsigned long long fma2(unsigned long long a,
                                                   unsigned long long b,
                                                   unsigned long long c) {
    unsigned long long d;
    asm("fma.rn.f32x2 %0, %1, %2, %3;" : "=l"(d) : "l"(a), "l"(b), "l"(c));
    return d;
}
__device__ __forceinline__ unsigned long long mul2(unsigned long long a,
                                                   unsigned long long b) {
    unsigned long long d;
    asm("mul.rn.f32x2 %0, %1, %2;" : "=l"(d) : "l"(a), "l"(b));
    return d;
}

__global__ __launch_bounds__(128, 10)
void mr_kernel(const float* __restrict__ rays_o,
               const float* __restrict__ rays_d,
               const float* __restrict__ levels,
               const float* __restrict__ W1,
               const float* __restrict__ b1,
               const float* __restrict__ W2,
               const float* __restrict__ b2,
               float* __restrict__ out,
               int N, int do_mask)
{
    // pair-interleaved raw weights, scaled by K = 2*log2(e):
    //   sPA[p] = (Kwx_j, Kwx_j1, Kwy_j, Kwy_j1)
    //   sPB[p] = (Kwz_j, Kwz_j1, Kb1_j, Kb1_j1)
    //   sM2[p] = (-2w2_j, -2w2_j1)
    __shared__ float4 sPA[NPAIR];
    __shared__ float4 sPB[NPAIR];
    __shared__ float2 sM2[NPAIR];
    __shared__ float  slev[LVL];
    __shared__ float  sw2sum;
    __shared__ float  sscal[WPB][SN];
    __shared__ float4 sGH[WPB][NPAIR];   // per-ray affine coeffs (g0,g1,h0,h1)

    const float K = 2.8853900817779268f;   // 2*log2(e)

    int tid = threadIdx.x;
    if (tid < NPAIR) {
        int j = 2*tid, j1 = j + 1;
        sPA[tid] = make_float4(K*W1[j], K*W1[j1], K*W1[HN + j], K*W1[HN + j1]);
        sPB[tid] = make_float4(K*W1[2*HN + j], K*W1[2*HN + j1], K*b1[j], K*b1[j1]);
        sM2[tid] = make_float2(-2.0f*W2[j], -2.0f*W2[j1]);
    }
    if (tid < LVL) slev[tid] = levels[tid];
    if (tid == 0) {
        float s = 0.0f;
        #pragma unroll 8
        for (int j = 0; j < HN; ++j) s += W2[j];
        sw2sum = s;
    }
    __syncthreads();

    float addc  = b2[0] + 1.0f;          // b2 + R0
    float cbase = addc + sw2sum;         // constant after the -2*w2*r fold

    int lane = tid & 31;
    int warp = tid >> 5;
    int ray  = blockIdx.x * WPB + warp;
    if (ray >= N) return;

    float ox = rays_o[ray*3+0], oy = rays_o[ray*3+1], oz = rays_o[ray*3+2];
    float dx = rays_d[ray*3+0], dy = rays_d[ray*3+1], dz = rays_d[ray*3+2];

    // sphere bounds
    float bq = ox*dx + oy*dy + oz*dz;
    float cq = ox*ox + oy*oy + oz*oz - 9.0f;
    float disc = bq*bq - cq;
    bool  hit = disc > 0.0f;
    float sq = sqrtf(hit ? disc : 1.0f);
    float dnear = fmaxf(-bq - sq, 0.0f);
    float dfar  = fminf(-bq + sq, 100.0f);
    bool  mask_bound = hit && (dnear < dfar);

    float* scal = sscal[warp];

    // ---------------- per-ray affine coefficients: pre_j(t) = g_j * t + h_j ----------------
    {
        ulonglong2 A  = *reinterpret_cast<const ulonglong2*>(&sPA[lane]); // (wx pair, wy pair)
        ulonglong2 Bv = *reinterpret_cast<const ulonglong2*>(&sPB[lane]); // (wz pair, b pair)
        unsigned long long DX2 = pk2(dx,dx), DY2 = pk2(dy,dy), DZ2 = pk2(dz,dz);
        unsigned long long OX2 = pk2(ox,ox), OY2 = pk2(oy,oy), OZ2 = pk2(oz,oz);
        unsigned long long G2 = fma2(A.x, DX2, fma2(A.y, DY2, mul2(Bv.x, DZ2)));
        unsigned long long H2 = fma2(A.x, OX2, fma2(A.y, OY2, fma2(Bv.x, OZ2, Bv.y)));
        ulonglong2 gh; gh.x = G2; gh.y = H2;
        *reinterpret_cast<ulonglong2*>(&sGH[warp][lane]) = gh;
    }
    __syncwarp();

    // ---------------- Phase A: 2 samples per lane, pair-group outer loop ----------------
    float t0 = (float)lane / 63.0f;
    float t1 = (float)(lane + 32) / 63.0f;
    float dd0 = dnear*(1.0f - t0) + dfar*t0;
    float dd1 = dnear*(1.0f - t1) + dfar*t1;
    unsigned long long DD0 = pk2(dd0, dd0);
    unsigned long long DD1 = pk2(dd1, dd1);
    // exact elementwise norms (reference boundary behavior)
    float nrm0, nrm1;
    {
        float x0 = fmaf(dx, dd0, ox), x1 = fmaf(dy, dd0, oy), x2 = fmaf(dz, dd0, oz);
        nrm0 = fast_sqrt(fmaf(x0, x0, fmaf(x1, x1, x2*x2)));
        float y0 = fmaf(dx, dd1, ox), y1 = fmaf(dy, dd1, oy), y2 = fmaf(dz, dd1, oz);
        nrm1 = fast_sqrt(fmaf(y0, y0, fmaf(y1, y1, y2*y2)));
    }
    float a00 = 0.0f, a01 = 0.0f, a10 = 0.0f, a11 = 0.0f;
    #pragma unroll 4
    for (int g = 0; g < 16; ++g) {
        ulonglong2 GH0 = *reinterpret_cast<const ulonglong2*>(&sGH[warp][2*g]);
        ulonglong2 GH1 = *reinterpret_cast<const ulonglong2*>(&sGH[warp][2*g+1]);
        float4 m2q = *reinterpret_cast<const float4*>(&sM2[2*g]);   // (m2_0,m2_1,m2_2,m2_3)
        float u01 = m2q.x + m2q.y;
        float u23 = m2q.z + m2q.w;
        // pre-activations for both samples
        unsigned long long pA0 = fma2(DD0, GH0.x, GH0.y);
        unsigned long long pB0 = fma2(DD0, GH1.x, GH1.y);
        unsigned long long pA1 = fma2(DD1, GH0.x, GH0.y);
        unsigned long long pB1 = fma2(DD1, GH1.x, GH1.y);
        float p00, p01, p02, p03, p10, p11, p12, p13;
        upk2(pA0, p00, p01); upk2(pB0, p02, p03);
        upk2(pA1, p10, p11); upk2(pB1, p12, p13);
        float e00 = fast_ex2(p00), e01 = fast_ex2(p01);
        float e02 = fast_ex2(p02), e03 = fast_ex2(p03);
        float e10 = fast_ex2(p10), e11 = fast_ex2(p11);
        float e12 = fast_ex2(p12), e13 = fast_ex2(p13);
        float A00 = 1.0f + e00, A02 = 1.0f + e02;
        float A10 = 1.0f + e10, A12 = 1.0f + e12;
        float b0a = fmaf(A00, e01, A00);     // (1+e00)(1+e01)
        float b0b = fmaf(A02, e03, A02);     // (1+e02)(1+e03)
        float b1a = fmaf(A10, e11, A10);
        float b1b = fmaf(A12, e13, A12);
        // one rcp for both samples: r = 1/(L*R), rL = 1/L, rR = 1/R
        float L  = b0a * b0b;
        float R  = b1a * b1b;
        float r  = fast_rcp(L * R);
        float rL = R * r;
        float rR = L * r;
        float q0a = b0b * rL, q0b = b0a * rL;
        float q1a = b1b * rR, q1b = b1a * rR;
        float N0a = fmaf(m2q.x, e01, fmaf(m2q.y, e00, u01));
        float N0b = fmaf(m2q.z, e03, fmaf(m2q.w, e02, u23));
        float N1a = fmaf(m2q.x, e11, fmaf(m2q.y, e10, u01));
        float N1b = fmaf(m2q.z, e13, fmaf(m2q.w, e12, u23));
        a00 = fmaf(N0a, q0a, a00);
        a01 = fmaf(N0b, q0b, a01);
        a10 = fmaf(N1a, q1a, a10);
        a11 = fmaf(N1b, q1b, a11);
    }
    float sv0 = (a00 + a01) + cbase - nrm0;
    float sv1 = (a10 + a11) + cbase - nrm1;
    scal[lane]      = sv0;
    scal[lane + 32] = sv1;
    unsigned vm0 = __ballot_sync(FULL, nrm0 < 3.0f);
    unsigned vm1 = __ballot_sync(FULL, nrm1 < 3.0f);
    // per-lane min (ascending s order: s=lane first, then s=lane+32; strict < keeps first)
    float minv = 3.402823466e38f;
    int   minj = 0;
    if (lane >= 1 && sv0 < minv) { minv = sv0; minj = lane - 1; }
    if (sv1 < minv)              { minv = sv1; minj = lane + 31; }
    __syncwarp();

    // warp-reduce argmin (first occurrence on ties -> smaller index)
    #pragma unroll
    for (int off = 16; off >= 1; off >>= 1) {
        float ov = __shfl_xor_sync(FULL, minv, off);
        int   oj = __shfl_xor_sync(FULL, minj, off);
        if (ov < minv || (ov == minv && oj < minj)) { minv = ov; minj = oj; }
    }

    // ---------------- Phase B: interval search, 8 lanes per level ----------------
    int   mylev = lane & 3;
    int   grp   = lane >> 2;
    float lval  = slev[mylev];
    float brank = -3.402823466e38f;
    int   bj    = 63;
    int   anyi  = 0;
    #pragma unroll
    for (int k = 0; k < 8; ++k) {
        int j = grp*8 + k;
        if (j < 63) {
            float sf = scal[j], sb = scal[j+1];
            float diff = lval - sb;
            float sgn = (diff > 0.0f) ? 1.0f : ((diff < 0.0f) ? -1.0f : 0.0f);
            float rank = sgn * (float)(63 - j);
            if (rank > brank) { brank = rank; bj = j; }   // ascending j -> first max kept
            unsigned wv  = (j  < 32) ? vm0 : vm1;
            unsigned wv1 = (j+1 < 32) ? vm0 : vm1;
            bool vj  = (wv  >> (j & 31)) & 1u;
            bool vj1 = (wv1 >> ((j+1) & 31)) & 1u;
            if ((sf >= lval) && (lval >= sb) && vj && vj1) anyi = 1;
        }
    }
    #pragma unroll
    for (int off = 4; off <= 16; off <<= 1) {
        float orank = __shfl_xor_sync(FULL, brank, off);
        int   obj   = __shfl_xor_sync(FULL, bj, off);
        int   oany  = __shfl_xor_sync(FULL, anyi, off);
        anyi |= oany;
        if (orank > brank || (orank == brank && obj < bj)) { brank = orank; bj = obj; }
    }
    int idxsel = anyi ? bj : minj;   // valid at lanes 0..3 (lane L holds level L)

    // ---------------- Phase C: all 4 levels concurrently, 8 lanes per level ----------------
    int levgrp = lane >> 3;          // my level (0..3)
    int sub    = lane & 7;           // my slot within the level group
    float lv   = slev[levgrp];
    int  idxL  = __shfl_sync(FULL, idxsel, levgrp);

    // my 4 unit-pairs: p = sub*4 .. sub*4+3; m2 hoisted into regs
    float4 m2a = *reinterpret_cast<const float4*>(&sM2[sub*4]);     // pairs 4s, 4s+1
    float4 m2b = *reinterpret_cast<const float4*>(&sM2[sub*4+2]);   // pairs 4s+2, 4s+3
    float ua01 = m2a.x + m2a.y, ua23 = m2a.z + m2a.w;
    float ub01 = m2b.x + m2b.y, ub23 = m2b.z + m2b.w;
    float wq = -0.5f * (ua01 + ua23 + ub01 + ub23);

    float tF = (float)idxL / 63.0f;
    float tB = (float)(idxL+1) / 63.0f;
    float d_front = dnear*(1.0f - tF) + dfar*tF;
    float d_back  = dnear*(1.0f - tB) + dfar*tB;
    float s_front = scal[idxL], s_back = scal[idxL+1];
    bool  m_int = (s_front >= lv) && (lv >= s_back);
    float sdiff = s_front - s_back;
    bool  mvd = fabsf(sdiff) > 1e-4f;
    bool  m_sec = m_int && mvd;
    float d_sec = ((lv - s_back)*d_front + (s_front - lv)*d_back) / (mvd ? sdiff : 1.0f);
    float d_init = m_sec ? d_sec : d_back;

    float dfs = d_front, dbs = d_back, sfs = s_front, sbs = s_back, dcur = d_init;
    #pragma unroll
    for (int it = 0; it < 4; ++it) {
        unsigned long long DC2 = pk2(dcur, dcur);
        float partial = wq;
        #pragma unroll
        for (int gg = 0; gg < 2; ++gg) {
            int p = sub*4 + gg*2;
            ulonglong2 GHa = *reinterpret_cast<const ulonglong2*>(&sGH[warp][p]);
            ulonglong2 GHb = *reinterpret_cast<const ulonglong2*>(&sGH[warp][p+1]);
            float4 m2q = gg ? m2b : m2a;
            float u01 = gg ? ub01 : ua01;
            float u23 = gg ? ub23 : ua23;
            unsigned long long pA = fma2(DC2, GHa.x, GHa.y);
            unsigned long long pB = fma2(DC2, GHb.x, GHb.y);
            float p0, p1, p2, p3;
            upk2(pA, p0, p1); upk2(pB, p2, p3);
            float e0 = fast_ex2(p0), e1 = fast_ex2(p1);
            float e2 = fast_ex2(p2), e3 = fast_ex2(p3);
            float A0 = 1.0f + e0, A2 = 1.0f + e2;
            float b01 = fmaf(A0, e1, A0);
            float b23 = fmaf(A2, e3, A2);
            float rp  = fast_rcp(b01 * b23);
            float q01 = b23 * rp;
            float q23 = b01 * rp;
            float N01 = fmaf(m2q.x, e1, fmaf(m2q.y, e0, u01));
            float N23 = fmaf(m2q.z, e3, fmaf(m2q.w, e2, u23));
            partial = fmaf(N01, q01, partial);
            partial = fmaf(N23, q23, partial);
        }
        // reduce over the 8 lanes of my level group (aligned; xor 1,2,4 stays in group)
        #pragma unroll
        for (int off = 1; off <= 4; off <<= 1)
            partial += __shfl_xor_sync(FULL, partial, off);   // identical across group
        // exact elementwise norm
        float x0 = fmaf(dx, dcur, ox);
        float x1 = fmaf(dy, dcur, oy);
        float x2 = fmaf(dz, dcur, oz);
        float nrm = fast_sqrt(fmaf(x0, x0, fmaf(x1, x1, x2*x2)));
        float s_mid = partial + addc - nrm;
        bool mv = nrm < 3.0f;
        bool upf = (s_mid > lv) && mv;
        bool upb = (s_mid < lv) && mv;
        if (upf) { dfs = dcur; sfs = s_mid; }
        if (upb) { dbs = dcur; sbs = s_mid; }
        float sd = sfs - sbs;
        bool ok = fabsf(sd) > 1e-4f;
        float dn = ((lv - sbs)*dfs + (sfs - lv)*dbs) / (ok ? sd : 1.0f);
        dcur = ok ? dn : dcur;
    }
    float dL = m_sec ? dcur : d_init;
    int   mL = m_int ? 1 : 0;

    // gather the 4 per-level results (levels live at lanes 0,8,16,24)
    float d0 = __shfl_sync(FULL, dL, 0);
    float d1 = __shfl_sync(FULL, dL, 8);
    float d2 = __shfl_sync(FULL, dL, 16);
    float d3 = __shfl_sync(FULL, dL, 24);
    int   m0 = __shfl_sync(FULL, mL, 0);
    int   m1 = __shfl_sync(FULL, mL, 8);
    int   m2v = __shfl_sync(FULL, mL, 16);
    int   m3 = __shfl_sync(FULL, mL, 24);

    // ---------------- stable ascending sort of 4 (adjacent swaps, strict <) ----------------
    #define CSW(da,ma,db,mb) do { if ((db) < (da)) { float _t=(da); (da)=(db); (db)=_t; int _m=(ma); (ma)=(mb); (mb)=_m; } } while(0)
    CSW(d0,m0,d1,m1); CSW(d1,m1,d2,m2v); CSW(d2,m2v,d3,m3);
    CSW(d0,m0,d1,m1); CSW(d1,m1,d2,m2v);
    CSW(d0,m0,d1,m1);
    #undef CSW

    if (lane == 0) {
        float4 dv = mask_bound ? make_float4(d0, d1, d2, d3)
                               : make_float4(0.f, 0.f, 0.f, 0.f);
        *reinterpret_cast<float4*>(out + (size_t)ray*4) = dv;
        if (do_mask) {
            float4 mv4 = mask_bound ? make_float4((float)m0, (float)m1, (float)m2v, (float)m3)
                                    : make_float4(0.f, 0.f, 0.f, 0.f);
            *reinterpret_cast<float4*>(out + (size_t)N*4 + (size_t)ray*4) = mv4;
        }
    }
}

extern "C" void kernel_launch(void* const* d_in, const int* in_sizes, int n_in,
                              void* d_out, int out_size) {
    const float* rays_o = (const float*)d_in[0];
    const float* rays_d = (const float*)d_in[1];
    const float* levels = (const float*)d_in[2];
    const float* W1     = (const float*)d_in[3];
    const float* b1     = (const float*)d_in[4];
    const float* W2     = (const float*)d_in[5];
    const float* b2     = (const float*)d_in[6];
    int N = in_sizes[0] / 3;
    int do_mask = (out_size >= 2 * N * LVL) ? 1 : 0;
    int blocks = (N + WPB - 1) / WPB;
    mr_kernel<<<blocks, 128>>>(rays_o, rays_d, levels, W1, b1, W2, b2,
                               (float*)d_out, N, do_mask);
}

// round 16
// speedup vs baseline: 1.1424x; 1.0660x over previous
#include <cuda_runtime.h>

#define FULL 0xffffffffu
#define WPB 4            // warps (rays) per block
#define HN 64
#define NPAIR 32
#define LVL 4
#define SN 64

__device__ __forceinline__ float fast_ex2(float x) {
    float y; asm("ex2.approx.f32 %0, %1;" : "=f"(y) : "f"(x)); return y;
}
__device__ __forceinline__ float fast_rcp(float x) {
    float y; asm("rcp.approx.f32 %0, %1;" : "=f"(y) : "f"(x)); return y;
}
__device__ __forceinline__ float fast_sqrt(float x) {
    float y; asm("sqrt.approx.f32 %0, %1;" : "=f"(y) : "f"(x)); return y;
}
__device__ __forceinline__ unsigned long long pk2(float lo, float hi) {
    unsigned long long r; asm("mov.b64 %0, {%1, %2};" : "=l"(r) : "f"(lo), "f"(hi)); return r;
}
__device__ __forceinline__ void upk2(unsigned long long v, float& lo, float& hi) {
    asm("mov.b64 {%0, %1}, %2;" : "=f"(lo), "=f"(hi) : "l"(v));
}
__device__ __forceinline__ unsigned long long fma2(unsigned long long a,
                                                   unsigned long long b,
                                                   unsigned long long c) {
    unsigned long long d;
    asm("fma.rn.f32x2 %0, %1, %2, %3;" : "=l"(d) : "l"(a), "l"(b), "l"(c));
    return d;
}
__device__ __forceinline__ unsigned long long mul2(unsigned long long a,
                                                   unsigned long long b) {
    unsigned long long d;
    asm("mul.rn.f32x2 %0, %1, %2;" : "=l"(d) : "l"(a), "l"(b));
    return d;
}

__global__ __launch_bounds__(128, 10)
void mr_kernel(const float* __restrict__ rays_o,
               const float* __restrict__ rays_d,
               const float* __restrict__ levels,
               const float* __restrict__ W1,
               const float* __restrict__ b1,
               const float* __restrict__ W2,
               const float* __restrict__ b2,
               float* __restrict__ out,
               int N, int do_mask)
{
    // pair-interleaved raw weights, scaled by K = 2*log2(e):
    //   sPA[p] = (Kwx_j, Kwx_j1, Kwy_j, Kwy_j1)
    //   sPB[p] = (Kwz_j, Kwz_j1, Kb1_j, Kb1_j1)
    //   sM2[p] = (-2w2_j, -2w2_j1)
    __shared__ float4 sPA[NPAIR];
    __shared__ float4 sPB[NPAIR];
    __shared__ float2 sM2[NPAIR];
    __shared__ float  slev[LVL];
    __shared__ float  sw2sum;
    __shared__ float  sscal[WPB][SN];
    __shared__ float4 sGH[WPB][NPAIR];   // per-ray affine coeffs (g0,g1,h0,h1)

    const float K = 2.8853900817779268f;   // 2*log2(e)

    int tid = threadIdx.x;
    if (tid < NPAIR) {
        int j = 2*tid, j1 = j + 1;
        sPA[tid] = make_float4(K*W1[j], K*W1[j1], K*W1[HN + j], K*W1[HN + j1]);
        sPB[tid] = make_float4(K*W1[2*HN + j], K*W1[2*HN + j1], K*b1[j], K*b1[j1]);
        sM2[tid] = make_float2(-2.0f*W2[j], -2.0f*W2[j1]);
    }
    if (tid < LVL) slev[tid] = levels[tid];
    if (tid == 0) {
        float s = 0.0f;
        #pragma unroll 8
        for (int j = 0; j < HN; ++j) s += W2[j];
        sw2sum = s;
    }
    __syncthreads();

    float addc  = b2[0] + 1.0f;          // b2 + R0
    float cbase = addc + sw2sum;         // constant after the -2*w2*r fold

    int lane = tid & 31;
    int warp = tid >> 5;
    int ray  = blockIdx.x * WPB + warp;
    if (ray >= N) return;

    float ox = rays_o[ray*3+0], oy = rays_o[ray*3+1], oz = rays_o[ray*3+2];
    float dx = rays_d[ray*3+0], dy = rays_d[ray*3+1], dz = rays_d[ray*3+2];

    // sphere bounds
    float bq = ox*dx + oy*dy + oz*dz;
    float cq = ox*ox + oy*oy + oz*oz - 9.0f;
    float disc = bq*bq - cq;
    bool  hit = disc > 0.0f;
    float sq = sqrtf(hit ? disc : 1.0f);
    float dnear = fmaxf(-bq - sq, 0.0f);
    float dfar  = fminf(-bq + sq, 100.0f);
    bool  mask_bound = hit && (dnear < dfar);

    float* scal = sscal[warp];

    // ---------------- per-ray affine coefficients: pre_j(t) = g_j * t + h_j ----------------
    {
        ulonglong2 A  = *reinterpret_cast<const ulonglong2*>(&sPA[lane]); // (wx pair, wy pair)
        ulonglong2 Bv = *reinterpret_cast<const ulonglong2*>(&sPB[lane]); // (wz pair, b pair)
        unsigned long long DX2 = pk2(dx,dx), DY2 = pk2(dy,dy), DZ2 = pk2(dz,dz);
        unsigned long long OX2 = pk2(ox,ox), OY2 = pk2(oy,oy), OZ2 = pk2(oz,oz);
        unsigned long long G2 = fma2(A.x, DX2, fma2(A.y, DY2, mul2(Bv.x, DZ2)));
        unsigned long long H2 = fma2(A.x, OX2, fma2(A.y, OY2, fma2(Bv.x, OZ2, Bv.y)));
        ulonglong2 gh; gh.x = G2; gh.y = H2;
        *reinterpret_cast<ulonglong2*>(&sGH[warp][lane]) = gh;
    }
    __syncwarp();

    // ---------------- Phase A: 2 samples per lane, pair-group outer loop ----------------
    float t0 = (float)lane / 63.0f;
    float t1 = (float)(lane + 32) / 63.0f;
    float dd0 = dnear*(1.0f - t0) + dfar*t0;
    float dd1 = dnear*(1.0f - t1) + dfar*t1;
    unsigned long long DD0 = pk2(dd0, dd0);
    unsigned long long DD1 = pk2(dd1, dd1);
    // exact elementwise norms (reference boundary behavior)
    float nrm0, nrm1;
    {
        float x0 = fmaf(dx, dd0, ox), x1 = fmaf(dy, dd0, oy), x2 = fmaf(dz, dd0, oz);
        nrm0 = fast_sqrt(fmaf(x0, x0, fmaf(x1, x1, x2*x2)));
        float y0 = fmaf(dx, dd1, ox), y1 = fmaf(dy, dd1, oy), y2 = fmaf(dz, dd1, oz);
        nrm1 = fast_sqrt(fmaf(y0, y0, fmaf(y1, y1, y2*y2)));
    }
    float acc0 = 0.0f, acc1 = 0.0f;
    #pragma unroll 4
    for (int g = 0; g < 16; ++g) {
        ulonglong2 GH0 = *reinterpret_cast<const ulonglong2*>(&sGH[warp][2*g]);
        ulonglong2 GH1 = *reinterpret_cast<const ulonglong2*>(&sGH[warp][2*g+1]);
        float4 m2q = *reinterpret_cast<const float4*>(&sM2[2*g]);   // (m2_0,m2_1,m2_2,m2_3)
        float u01 = m2q.x + m2q.y;
        float u23 = m2q.z + m2q.w;
        // pre-activations for both samples
        unsigned long long pA0 = fma2(DD0, GH0.x, GH0.y);
        unsigned long long pB0 = fma2(DD0, GH1.x, GH1.y);
        unsigned long long pA1 = fma2(DD1, GH0.x, GH0.y);
        unsigned long long pB1 = fma2(DD1, GH1.x, GH1.y);
        float p00, p01, p02, p03, p10, p11, p12, p13;
        upk2(pA0, p00, p01); upk2(pB0, p02, p03);
        upk2(pA1, p10, p11); upk2(pB1, p12, p13);
        float e00 = fast_ex2(p00), e01 = fast_ex2(p01);
        float e02 = fast_ex2(p02), e03 = fast_ex2(p03);
        float e10 = fast_ex2(p10), e11 = fast_ex2(p11);
        float e12 = fast_ex2(p12), e13 = fast_ex2(p13);
        float A00 = 1.0f + e00, A02 = 1.0f + e02;
        float A10 = 1.0f + e10, A12 = 1.0f + e12;
        float b0a = fmaf(A00, e01, A00);     // (1+e00)(1+e01)
        float b0b = fmaf(A02, e03, A02);     // (1+e02)(1+e03)
        float b1a = fmaf(A10, e11, A10);
        float b1b = fmaf(A12, e13, A12);
        // one rcp for both samples; numerators combined over common denominators
        float L  = b0a * b0b;
        float R  = b1a * b1b;
        float r  = fast_rcp(L * R);
        float N0a = fmaf(m2q.x, e01, fmaf(m2q.y, e00, u01));
        float N0b = fmaf(m2q.z, e03, fmaf(m2q.w, e02, u23));
        float N1a = fmaf(m2q.x, e11, fmaf(m2q.y, e10, u01));
        float N1b = fmaf(m2q.z, e13, fmaf(m2q.w, e12, u23));
        float S0 = N0a * b0b;  S0 = fmaf(N0b, b0a, S0);   // (N0a/b0a + N0b/b0b)·L
        float S1 = N1a * b1b;  S1 = fmaf(N1b, b1a, S1);   // (N1a/b1a + N1b/b1b)·R
        float T0 = S0 * R;
        float T1 = S1 * L;
        acc0 = fmaf(T0, r, acc0);
        acc1 = fmaf(T1, r, acc1);
    }
    float sv0 = acc0 + cbase - nrm0;
    float sv1 = acc1 + cbase - nrm1;
    scal[lane]      = sv0;
    scal[lane + 32] = sv1;
    unsigned vm0 = __ballot_sync(FULL, nrm0 < 3.0f);
    unsigned vm1 = __ballot_sync(FULL, nrm1 < 3.0f);
    // per-lane min (ascending s order: s=lane first, then s=lane+32; strict < keeps first)
    float minv = 3.402823466e38f;
    int   minj = 0;
    if (lane >= 1 && sv0 < minv) { minv = sv0; minj = lane - 1; }
    if (sv1 < minv)              { minv = sv1; minj = lane + 31; }
    __syncwarp();

    // warp-reduce argmin (first occurrence on ties -> smaller index)
    #pragma unroll
    for (int off = 16; off >= 1; off >>= 1) {
        float ov = __shfl_xor_sync(FULL, minv, off);
        int   oj = __shfl_xor_sync(FULL, minj, off);
        if (ov < minv || (ov == minv && oj < minj)) { minv = ov; minj = oj; }
    }

    // ---------------- Phase B: interval search, 8 lanes per level ----------------
    unsigned long long vmall = (unsigned long long)vm0 | ((unsigned long long)vm1 << 32);
    unsigned long long pvall = vmall & (vmall >> 1);   // bit j = valid_j & valid_{j+1}
    int   mylev = lane & 3;
    int   grp   = lane >> 2;
    unsigned pv8 = (unsigned)(pvall >> (grp*8));
    float lval  = slev[mylev];
    float brank = -3.402823466e38f;
    int   bj    = 63;
    int   anyi  = 0;
    #pragma unroll
    for (int k = 0; k < 8; ++k) {
        int j = grp*8 + k;
        if (j < 63) {
            float sf = scal[j], sb = scal[j+1];
            bool  gt = lval > sb;
            bool  lt = lval < sb;
            float sgn = gt ? 1.0f : (lt ? -1.0f : 0.0f);
            float rank = sgn * (float)(63 - j);
            if (rank > brank) { brank = rank; bj = j; }   // ascending j -> first max kept
            if ((sf >= lval) && !lt && ((pv8 >> k) & 1u)) anyi = 1;
        }
    }
    #pragma unroll
    for (int off = 4; off <= 16; off <<= 1) {
        float orank = __shfl_xor_sync(FULL, brank, off);
        int   obj   = __shfl_xor_sync(FULL, bj, off);
        int   oany  = __shfl_xor_sync(FULL, anyi, off);
        anyi |= oany;
        if (orank > brank || (orank == brank && obj < bj)) { brank = orank; bj = obj; }
    }
    int idxsel = anyi ? bj : minj;   // valid at lanes 0..3 (lane L holds level L)

    // ---------------- Phase C: all 4 levels concurrently, 8 lanes per level ----------------
    int levgrp = lane >> 3;          // my level (0..3)
    int sub    = lane & 7;           // my slot within the level group
    float lv   = slev[levgrp];
    int  idxL  = __shfl_sync(FULL, idxsel, levgrp);

    // my 4 unit-pairs: p = sub*4 .. sub*4+3; m2 hoisted into regs
    float4 m2a = *reinterpret_cast<const float4*>(&sM2[sub*4]);     // pairs 4s, 4s+1
    float4 m2b = *reinterpret_cast<const float4*>(&sM2[sub*4+2]);   // pairs 4s+2, 4s+3
    float ua01 = m2a.x + m2a.y, ua23 = m2a.z + m2a.w;
    float ub01 = m2b.x + m2b.y, ub23 = m2b.z + m2b.w;
    float wq = -0.5f * (ua01 + ua23 + ub01 + ub23);

    float tF = (float)idxL / 63.0f;
    float tB = (float)(idxL+1) / 63.0f;
    float d_front = dnear*(1.0f - tF) + dfar*tF;
    float d_back  = dnear*(1.0f - tB) + dfar*tB;
    float s_front = scal[idxL], s_back = scal[idxL+1];
    bool  m_int = (s_front >= lv) && (lv >= s_back);
    float sdiff = s_front - s_back;
    bool  mvd = fabsf(sdiff) > 1e-4f;
    bool  m_sec = m_int && mvd;
    float d_sec = ((lv - s_back)*d_front + (s_front - lv)*d_back) / (mvd ? sdiff : 1.0f);
    float d_init = m_sec ? d_sec : d_back;

    float dfs = d_front, dbs = d_back, sfs = s_front, sbs = s_back, dcur = d_init;
    #pragma unroll
    for (int it = 0; it < 4; ++it) {
        unsigned long long DC2 = pk2(dcur, dcur);
        int p = sub*4;
        ulonglong2 GH0 = *reinterpret_cast<const ulonglong2*>(&sGH[warp][p]);
        ulonglong2 GH1 = *reinterpret_cast<const ulonglong2*>(&sGH[warp][p+1]);
        ulonglong2 GH2 = *reinterpret_cast<const ulonglong2*>(&sGH[warp][p+2]);
        ulonglong2 GH3 = *reinterpret_cast<const ulonglong2*>(&sGH[warp][p+3]);
        unsigned long long pA = fma2(DC2, GH0.x, GH0.y);
        unsigned long long pB = fma2(DC2, GH1.x, GH1.y);
        unsigned long long pC = fma2(DC2, GH2.x, GH2.y);
        unsigned long long pD = fma2(DC2, GH3.x, GH3.y);
        float p0, p1, p2, p3, p4, p5, p6, p7;
        upk2(pA, p0, p1); upk2(pB, p2, p3);
        upk2(pC, p4, p5); upk2(pD, p6, p7);
        float e0 = fast_ex2(p0), e1 = fast_ex2(p1);
        float e2 = fast_ex2(p2), e3 = fast_ex2(p3);
        float e4 = fast_ex2(p4), e5 = fast_ex2(p5);
        float e6 = fast_ex2(p6), e7 = fast_ex2(p7);
        float A0 = 1.0f + e0, A2 = 1.0f + e2, A4 = 1.0f + e4, A6 = 1.0f + e6;
        float b0 = fmaf(A0, e1, A0);
        float b1 = fmaf(A2, e3, A2);
        float b2f = fmaf(A4, e5, A4);
        float b3 = fmaf(A6, e7, A6);
        float P1 = b0 * b1;
        float P2 = b2f * b3;
        float r  = fast_rcp(P1 * P2);
        float N0 = fmaf(m2a.x, e1, fmaf(m2a.y, e0, ua01));
        float N1 = fmaf(m2a.z, e3, fmaf(m2a.w, e2, ua23));
        float N2 = fmaf(m2b.x, e5, fmaf(m2b.y, e4, ub01));
        float N3 = fmaf(m2b.z, e7, fmaf(m2b.w, e6, ub23));
        float S1 = N0 * b1;  S1 = fmaf(N1, b0, S1);
        float S2 = N2 * b3;  S2 = fmaf(N3, b2f, S2);
        float T  = S1 * P2;  T  = fmaf(S2, P1, T);
        float partial = fmaf(T, r, wq);
        // reduce over the 8 lanes of my level group (aligned; xor 1,2,4 stays in group)
        #pragma unroll
        for (int off = 1; off <= 4; off <<= 1)
            partial += __shfl_xor_sync(FULL, partial, off);   // identical across group
        // exact elementwise norm
        float x0 = fmaf(dx, dcur, ox);
        float x1 = fmaf(dy, dcur, oy);
        float x2 = fmaf(dz, dcur, oz);
        float nrm = fast_sqrt(fmaf(x0, x0, fmaf(x1, x1, x2*x2)));
        float s_mid = partial + addc - nrm;
        bool mv = nrm < 3.0f;
        bool upf = (s_mid > lv) && mv;
        bool upb = (s_mid < lv) && mv;
        if (upf) { dfs = dcur; sfs = s_mid; }
        if (upb) { dbs = dcur; sbs = s_mid; }
        float sd = sfs - sbs;
        bool ok = fabsf(sd) > 1e-4f;
        float dn = ((lv - sbs)*dfs + (sfs - lv)*dbs) / (ok ? sd : 1.0f);
        dcur = ok ? dn : dcur;
    }
    float dL = m_sec ? dcur : d_init;
    int   mL = m_int ? 1 : 0;

    // gather the 4 per-level results (levels live at lanes 0,8,16,24)
    float d0 = __shfl_sync(FULL, dL, 0);
    float d1 = __shfl_sync(FULL, dL, 8);
    float d2 = __shfl_sync(FULL, dL, 16);
    float d3 = __shfl_sync(FULL, dL, 24);
    int   m0 = __shfl_sync(FULL, mL, 0);
    int   m1 = __shfl_sync(FULL, mL, 8);
    int   m2v = __shfl_sync(FULL, mL, 16);
    int   m3 = __shfl_sync(FULL, mL, 24);

    // ---------------- stable ascending sort of 4 (adjacent swaps, strict <) ----------------
    #define CSW(da,ma,db,mb) do { if ((db) < (da)) { float _t=(da); (da)=(db); (db)=_t; int _m=(ma); (ma)=(mb); (mb)=_m; } } while(0)
    CSW(d0,m0,d1,m1); CSW(d1,m1,d2,m2v); CSW(d2,m2v,d3,m3);
    CSW(d0,m0,d1,m1); CSW(d1,m1,d2,m2v);
    CSW(d0,m0,d1,m1);
    #undef CSW

    if (lane == 0) {
        float4 dv = mask_bound ? make_float4(d0, d1, d2, d3)
                               : make_float4(0.f, 0.f, 0.f, 0.f);
        *reinterpret_cast<float4*>(out + (size_t)ray*4) = dv;
        if (do_mask) {
            float4 mv4 = mask_bound ? make_float4((float)m0, (float)m1, (float)m2v, (float)m3)
                                    : make_float4(0.f, 0.f, 0.f, 0.f);
            *reinterpret_cast<float4*>(out + (size_t)N*4 + (size_t)ray*4) = mv4;
        }
    }
}

extern "C" void kernel_launch(void* const* d_in, const int* in_sizes, int n_in,
                              void* d_out, int out_size) {
    const float* rays_o = (const float*)d_in[0];
    const float* rays_d = (const float*)d_in[1];
    const float* levels = (const float*)d_in[2];
    const float* W1     = (const float*)d_in[3];
    const float* b1     = (const float*)d_in[4];
    const float* W2     = (const float*)d_in[5];
    const float* b2     = (const float*)d_in[6];
    int N = in_sizes[0] / 3;
    int do_mask = (out_size >= 2 * N * LVL) ? 1 : 0;
    int blocks = (N + WPB - 1) / WPB;
    mr_kernel<<<blocks, 128>>>(rays_o, rays_d, levels, W1, b1, W2, b2,
                               (float*)d_out, N, do_mask);
}